// round 2
// baseline (speedup 1.0000x reference)
#include <cuda_runtime.h>

#define EPS 1e-5f
#define SLOPE 0.2f

constexpr int N1 = 10242, N2 = 40962, N3 = 163842;
constexpr int NT = 256;
constexpr int NB = 444;            // 148 SMs * 3 co-resident blocks
constexpr int GS = NB * NT;        // grid stride

// Scratch (allocation-free)
__device__ float g_xA[N3 * 8];
__device__ float g_xB[N3 * 8];
__device__ float g_part[NB * 16];
__device__ unsigned g_bar[8];      // monotonic ticket counters (zero-init)

// ---------------------------------------------------------------------------
// Grid-wide barrier: monotonic counter, passes when count % NB == 0.
// Replays are stream-serialized, so counters stay multiples of NB between
// launches; no reset needed (wraps only after ~9.6M launches).
// ---------------------------------------------------------------------------
__device__ __forceinline__ void gridsync(int slot) {
    __syncthreads();
    if (threadIdx.x == 0) {
        __threadfence();
        unsigned t = atomicAdd(&g_bar[slot], 1u) + 1u;
        if (t % NB != 0u) {
            volatile unsigned* p = &g_bar[slot];
            while ((*p) % NB != 0u) __nanosleep(64);
        }
        __threadfence();
    }
    __syncthreads();
}

// ---------------------------------------------------------------------------
// Block-reduce per-thread (sum, sum^2) and publish per-block partials.
// s_acc must be zeroed (with a barrier) before the phase's work loop.
// ---------------------------------------------------------------------------
template <int C>
__device__ __forceinline__ void stats_flush(const float* s1, const float* s2,
                                            float* s_acc) {
#pragma unroll
    for (int c = 0; c < C; c++) {
        float v = s1[c], v2 = s2[c];
#pragma unroll
        for (int o = 16; o > 0; o >>= 1) {
            v  += __shfl_down_sync(0xffffffffu, v,  o);
            v2 += __shfl_down_sync(0xffffffffu, v2, o);
        }
        if ((threadIdx.x & 31) == 0) {
            atomicAdd(&s_acc[c], v);
            atomicAdd(&s_acc[C + c], v2);
        }
    }
    __syncthreads();
    if (threadIdx.x < 2 * C) g_part[blockIdx.x * 16 + threadIdx.x] = s_acc[threadIdx.x];
}

// ---------------------------------------------------------------------------
// Redundant per-block finalize: partials -> sp[0..C)=scale, sp[8..8+C)=shift
// ---------------------------------------------------------------------------
template <int C>
__device__ __forceinline__ void finalize(float n, const float* __restrict__ g,
                                         const float* __restrict__ b,
                                         float* sp, float* s) {
    int tid = threadIdx.x;
    if (tid < 2 * C) s[tid] = 0.f;
    __syncthreads();
    float loc[2 * C];
#pragma unroll
    for (int i = 0; i < 2 * C; i++) loc[i] = 0.f;
    for (int blk = tid; blk < NB; blk += NT)
#pragma unroll
        for (int i = 0; i < 2 * C; i++) loc[i] += __ldcg(&g_part[blk * 16 + i]);
#pragma unroll
    for (int i = 0; i < 2 * C; i++) {
        float v = loc[i];
#pragma unroll
        for (int o = 16; o > 0; o >>= 1) v += __shfl_down_sync(0xffffffffu, v, o);
        if ((tid & 31) == 0) atomicAdd(&s[i], v);
    }
    __syncthreads();
    if (tid < C) {
        float m = s[tid] / n;
        float var = s[C + tid] / n - m * m;
        float sc = g[tid] * rsqrtf(var + EPS);
        sp[tid] = sc;
        sp[8 + tid] = b[tid] - m * sc;
    }
    __syncthreads();
}

// ---------------------------------------------------------------------------
// y-row on demand for upconv (x read cross-phase -> __ldcg)
// ---------------------------------------------------------------------------
__device__ __forceinline__ void yrow(const float* __restrict__ x,
                                     const float* sw, const float* sb,
                                     const float* sp, int idx, float* y) {
    int v = idx / 7;
    int j = idx - 7 * v;
    float xn[3];
#pragma unroll
    for (int k = 0; k < 3; k++) {
        float t = __ldcg(&x[3 * v + k]) * sp[k] + sp[8 + k];
        xn[k] = t >= 0.f ? t : SLOPE * t;
    }
#pragma unroll
    for (int c = 0; c < 3; c++) {
        int r = 3 * j + c;
        y[c] = sb[r] + xn[0] * sw[3 * r] + xn[1] * sw[3 * r + 1] + xn[2] * sw[3 * r + 2];
    }
}

// ---------------------------------------------------------------------------
// Upconv phase (grid-stride). Reference's reshape(-1,3,2).mean(-1) pairs
// INTERLEAVED channels across rows down[2e], down[2e+1].
// ---------------------------------------------------------------------------
__device__ __forceinline__ void upconv_phase(
    const float* __restrict__ x, const float* __restrict__ w,
    const float* __restrict__ b, const int* __restrict__ top,
    const int* __restrict__ down, int R, int Nout, float* __restrict__ out,
    float* sw, float* sb, const float* sp, float* s_acc) {
    int tid = threadIdx.x;
    if (tid < 63) sw[tid] = w[tid];
    if (tid < 21) sb[tid] = b[tid];
    if (tid < 16) s_acc[tid] = 0.f;
    __syncthreads();

    float s1[3] = {0.f, 0.f, 0.f}, s2[3] = {0.f, 0.f, 0.f};
    for (int t = blockIdx.x * NT + tid; t < Nout; t += GS) {
        float vals[3];
        if (t < R) {
            yrow(x, sw, sb, sp, __ldg(&top[t]), vals);
        } else {
            int e = t - R;
            int i0 = __ldg(&down[2 * e]), i1 = __ldg(&down[2 * e + 1]);
            float ya[3], yb[3];
            yrow(x, sw, sb, sp, i0, ya);
            yrow(x, sw, sb, sp, i1, yb);
            vals[0] = 0.5f * (ya[0] + ya[1]);
            vals[1] = 0.5f * (ya[2] + yb[0]);
            vals[2] = 0.5f * (yb[1] + yb[2]);
        }
        out[3 * t]     = vals[0];
        out[3 * t + 1] = vals[1];
        out[3 * t + 2] = vals[2];
#pragma unroll
        for (int c = 0; c < 3; c++) { s1[c] += vals[c]; s2[c] += vals[c] * vals[c]; }
    }
    stats_flush<3>(s1, s2, s_acc);
}

// ---------------------------------------------------------------------------
// One-ring conv phase (grid-stride)
// ---------------------------------------------------------------------------
template <int CIN, int COUT, bool STATS>
__device__ __forceinline__ void onering_phase(
    const float* __restrict__ x, const float* __restrict__ w,
    const float* __restrict__ b, const int* __restrict__ neigh,
    float* __restrict__ out, float* sw, float* sb, const float* sp,
    float* s_acc) {
    constexpr int WTOT = COUT * 7 * CIN;
    int tid = threadIdx.x;
    for (int i = tid; i < WTOT; i += NT) sw[i] = w[i];
    if (tid < COUT) sb[tid] = b[tid];
    if (tid < 16) s_acc[tid] = 0.f;
    __syncthreads();

    float s1[COUT], s2[COUT];
#pragma unroll
    for (int o = 0; o < COUT; o++) { s1[o] = 0.f; s2[o] = 0.f; }

    for (int n = blockIdx.x * NT + tid; n < N3; n += GS) {
        float acc[COUT];
#pragma unroll
        for (int o = 0; o < COUT; o++) acc[o] = sb[o];
#pragma unroll
        for (int j = 0; j < 7; j++) {
            int v = __ldg(&neigh[7 * n + j]);
            float xn[CIN];
            if (CIN == 8) {
                const float4* p = reinterpret_cast<const float4*>(x) + 2 * (size_t)v;
                float4 a = __ldcg(p), c4 = __ldcg(p + 1);
                float raw[8] = {a.x, a.y, a.z, a.w, c4.x, c4.y, c4.z, c4.w};
#pragma unroll
                for (int c = 0; c < CIN; c++) {
                    float t = raw[c] * sp[c] + sp[8 + c];
                    xn[c] = t >= 0.f ? t : SLOPE * t;
                }
            } else {
#pragma unroll
                for (int c = 0; c < CIN; c++) {
                    float t = __ldcg(&x[(size_t)CIN * v + c]) * sp[c] + sp[8 + c];
                    xn[c] = t >= 0.f ? t : SLOPE * t;
                }
            }
#pragma unroll
            for (int o = 0; o < COUT; o++)
#pragma unroll
                for (int c = 0; c < CIN; c++)
                    acc[o] += xn[c] * sw[o * 7 * CIN + j * CIN + c];
        }
#pragma unroll
        for (int o = 0; o < COUT; o++) out[(size_t)COUT * n + o] = acc[o];
        if (STATS) {
#pragma unroll
            for (int o = 0; o < COUT; o++) { s1[o] += acc[o]; s2[o] += acc[o] * acc[o]; }
        }
    }
    if (STATS) stats_flush<COUT>(s1, s2, s_acc);
}

// ---------------------------------------------------------------------------
// The whole network in ONE persistent kernel with 5 grid syncs.
// ---------------------------------------------------------------------------
__global__ void __launch_bounds__(NT, 3) atlas_kernel(
    const float* __restrict__ age, const float* __restrict__ aw,
    const float* __restrict__ ab, const float* __restrict__ fcw,
    const float* __restrict__ fcb,
    const float* __restrict__ bnu0g, const float* __restrict__ bnu0b,
    const float* __restrict__ u0w, const float* __restrict__ u0b,
    const float* __restrict__ bnu1g, const float* __restrict__ bnu1b,
    const float* __restrict__ u1w, const float* __restrict__ u1b,
    const float* __restrict__ bn0g, const float* __restrict__ bn0b,
    const float* __restrict__ c0w, const float* __restrict__ c0b,
    const float* __restrict__ bn1g, const float* __restrict__ bn1b,
    const float* __restrict__ c1w, const float* __restrict__ c1b,
    const float* __restrict__ bn2g, const float* __restrict__ bn2b,
    const float* __restrict__ c2w, const float* __restrict__ c2b,
    const int* __restrict__ top0, const int* __restrict__ down0,
    const int* __restrict__ top1, const int* __restrict__ down1,
    const int* __restrict__ neigh, float* __restrict__ d_out) {
    __shared__ float sw[448];
    __shared__ float sb[24];
    __shared__ float sp[16];
    __shared__ float s_acc[16];
    __shared__ float h[64];
    int tid = threadIdx.x;

    // ---- Phase 1: fc -> g_xA (N1 x 3) + stats ----
    if (tid < 64) h[tid] = age[0] * aw[tid] + ab[tid];
    if (tid < 16) s_acc[tid] = 0.f;
    __syncthreads();
    {
        float s1[3] = {0.f, 0.f, 0.f}, s2[3] = {0.f, 0.f, 0.f};
        for (int v = blockIdx.x * NT + tid; v < N1; v += GS) {
#pragma unroll
            for (int c = 0; c < 3; c++) {
                int r = 3 * v + c;
                float acc = fcb[r];
                const float4* wr = reinterpret_cast<const float4*>(fcw + (size_t)r * 64);
#pragma unroll
                for (int j = 0; j < 16; j++) {
                    float4 w4 = wr[j];
                    acc += w4.x * h[4 * j] + w4.y * h[4 * j + 1] +
                           w4.z * h[4 * j + 2] + w4.w * h[4 * j + 3];
                }
                g_xA[r] = acc;
                s1[c] += acc; s2[c] += acc * acc;
            }
        }
        stats_flush<3>(s1, s2, s_acc);
    }
    gridsync(0);
    finalize<3>((float)N1, bnu0g, bnu0b, sp, s_acc);

    // ---- Phase 2: upconv0  g_xA(N1) -> g_xB(N2) ----
    upconv_phase(g_xA, u0w, u0b, top0, down0, N1, N2, g_xB, sw, sb, sp, s_acc);
    gridsync(1);
    finalize<3>((float)N2, bnu1g, bnu1b, sp, s_acc);

    // ---- Phase 3: upconv1  g_xB(N2) -> g_xA(N3) ----
    upconv_phase(g_xB, u1w, u1b, top1, down1, N2, N3, g_xA, sw, sb, sp, s_acc);
    gridsync(2);
    finalize<3>((float)N3, bn0g, bn0b, sp, s_acc);

    // ---- Phase 4: onering 3->8  g_xA -> g_xB ----
    onering_phase<3, 8, true>(g_xA, c0w, c0b, neigh, g_xB, sw, sb, sp, s_acc);
    gridsync(3);
    finalize<8>((float)N3, bn1g, bn1b, sp, s_acc);

    // ---- Phase 5: onering 8->8  g_xB -> g_xA ----
    onering_phase<8, 8, true>(g_xB, c1w, c1b, neigh, g_xA, sw, sb, sp, s_acc);
    gridsync(4);
    finalize<8>((float)N3, bn2g, bn2b, sp, s_acc);

    // ---- Phase 6: onering 8->2  g_xA -> d_out ----
    onering_phase<8, 2, false>(g_xA, c2w, c2b, neigh, d_out, sw, sb, sp, s_acc);
}

extern "C" void kernel_launch(void* const* d_in, const int* in_sizes, int n_in,
                              void* d_out, int out_size) {
    atlas_kernel<<<NB, NT>>>(
        (const float*)d_in[0], (const float*)d_in[1], (const float*)d_in[2],
        (const float*)d_in[3], (const float*)d_in[4],
        (const float*)d_in[5], (const float*)d_in[6],
        (const float*)d_in[7], (const float*)d_in[8],
        (const float*)d_in[9], (const float*)d_in[10],
        (const float*)d_in[11], (const float*)d_in[12],
        (const float*)d_in[13], (const float*)d_in[14],
        (const float*)d_in[15], (const float*)d_in[16],
        (const float*)d_in[17], (const float*)d_in[18],
        (const float*)d_in[19], (const float*)d_in[20],
        (const float*)d_in[21], (const float*)d_in[22],
        (const float*)d_in[23], (const float*)d_in[24],
        (const int*)d_in[25], (const int*)d_in[26],
        (const int*)d_in[27], (const int*)d_in[28],
        (const int*)d_in[29], (float*)d_out);
}

// round 4
// speedup vs baseline: 1.4030x; 1.4030x over previous
#include <cuda_runtime.h>

#define EPS 1e-5f
#define SLOPE 0.2f

constexpr int N1 = 10242, N2 = 40962, N3 = 163842;
constexpr int NT = 256;
constexpr int MAXB = 704;

// Scratch (allocation-free)
__device__ float g_xA[N3 * 8];
__device__ float g_xB[N3 * 8];
__device__ float g_part[MAXB * 16];
__device__ float g_sp[16];        // scale[0..7], shift[8..15] for current phase
__device__ unsigned g_tick[8];    // self-resetting ticket counters

// ---------------------------------------------------------------------------
// Producer-side stats: block-reduce (sum,sum^2), publish partials, last block
// folds partials -> g_sp (deterministic: fixed-order single-block reduction).
// Must be called by ALL threads of every block (uniform control flow).
// ---------------------------------------------------------------------------
template <int C>
__device__ __forceinline__ void stats_publish(const float* s1, const float* s2,
                                              float* s_acc, int nb, float n,
                                              const float* __restrict__ g,
                                              const float* __restrict__ b,
                                              int phase) {
    int tid = threadIdx.x;
#pragma unroll
    for (int c = 0; c < C; c++) {
        float v = s1[c], v2 = s2[c];
#pragma unroll
        for (int o = 16; o > 0; o >>= 1) {
            v  += __shfl_down_sync(0xffffffffu, v,  o);
            v2 += __shfl_down_sync(0xffffffffu, v2, o);
        }
        if ((tid & 31) == 0) {
            atomicAdd(&s_acc[c], v);
            atomicAdd(&s_acc[C + c], v2);
        }
    }
    __syncthreads();
    if (tid < 2 * C) g_part[blockIdx.x * 16 + tid] = s_acc[tid];
    __threadfence();
    __shared__ unsigned lastf;
    if (tid == 0) lastf = (atomicAdd(&g_tick[phase], 1u) == (unsigned)(nb - 1)) ? 1u : 0u;
    __syncthreads();
    if (lastf) {
        float loc[2 * C];
#pragma unroll
        for (int i = 0; i < 2 * C; i++) loc[i] = 0.f;
        for (int blk = tid; blk < nb; blk += NT)
#pragma unroll
            for (int i = 0; i < 2 * C; i++) loc[i] += g_part[blk * 16 + i];
        __syncthreads();
        if (tid < 2 * C) s_acc[tid] = 0.f;
        __syncthreads();
#pragma unroll
        for (int i = 0; i < 2 * C; i++) {
            float v = loc[i];
#pragma unroll
            for (int o = 16; o > 0; o >>= 1) v += __shfl_down_sync(0xffffffffu, v, o);
            if ((tid & 31) == 0) atomicAdd(&s_acc[i], v);
        }
        __syncthreads();
        if (tid < 8) {
            float sc = 0.f, sh = 0.f;
            if (tid < C) {
                float m = s_acc[tid] / n;
                float var = s_acc[C + tid] / n - m * m;
                sc = g[tid] * rsqrtf(var + EPS);
                sh = b[tid] - m * sc;
            }
            g_sp[tid] = sc;
            g_sp[8 + tid] = sh;
        }
        if (tid == 0) {
            __threadfence();
            g_tick[phase] = 0u;   // self-reset for next graph replay
        }
    }
}

// Consumer head: load scale/shift (published by previous launch) into shared.
__device__ __forceinline__ void load_sp(float* sp) {
    if (threadIdx.x < 16) sp[threadIdx.x] = g_sp[threadIdx.x];
}

// ---------------------------------------------------------------------------
// K1: fc -> xA (stride 4, padded) + stats publish (phase 0)
// ---------------------------------------------------------------------------
__global__ void __launch_bounds__(NT) k_fc(
    const float* __restrict__ age, const float* __restrict__ aw,
    const float* __restrict__ ab, const float* __restrict__ fcw,
    const float* __restrict__ fcb, float* __restrict__ out,
    const float* __restrict__ bng, const float* __restrict__ bnb) {
    __shared__ float h[64];
    __shared__ float s_acc[16];
    int tid = threadIdx.x;
    if (tid < 64) h[tid] = age[0] * aw[tid] + ab[tid];
    if (tid < 16) s_acc[tid] = 0.f;
    __syncthreads();

    int v = blockIdx.x * NT + tid;
    float vals[3] = {0.f, 0.f, 0.f};
    if (v < N1) {
#pragma unroll
        for (int c = 0; c < 3; c++) {
            int r = 3 * v + c;
            float acc = fcb[r];
            const float4* wr = reinterpret_cast<const float4*>(fcw) + (size_t)r * 16;
#pragma unroll
            for (int j = 0; j < 16; j++) {
                float4 w4 = __ldg(wr + j);
                acc += w4.x * h[4 * j] + w4.y * h[4 * j + 1] +
                       w4.z * h[4 * j + 2] + w4.w * h[4 * j + 3];
            }
            vals[c] = acc;
        }
        reinterpret_cast<float4*>(out)[v] = make_float4(vals[0], vals[1], vals[2], 0.f);
    }
    float s2[3] = {vals[0] * vals[0], vals[1] * vals[1], vals[2] * vals[2]};
    stats_publish<3>(vals, s2, s_acc, (N1 + NT - 1) / NT, (float)N1, bng, bnb, 0);
}

// ---------------------------------------------------------------------------
// Upconv: x padded stride-4 in, stride-4 out. Reference's reshape(-1,3,2)
// .mean(-1) pairs INTERLEAVED channels across rows down[2e], down[2e+1].
// ---------------------------------------------------------------------------
__device__ __forceinline__ void yrow(const float* __restrict__ x4,
                                     const float* sw, const float* sb,
                                     const float* sp, int idx, float* y) {
    int v = idx / 7;
    int j = idx - 7 * v;
    float4 xv = __ldg(reinterpret_cast<const float4*>(x4) + v);
    float raw[3] = {xv.x, xv.y, xv.z};
    float xn[3];
#pragma unroll
    for (int k = 0; k < 3; k++) {
        float t = raw[k] * sp[k] + sp[8 + k];
        xn[k] = t >= 0.f ? t : SLOPE * t;
    }
#pragma unroll
    for (int c = 0; c < 3; c++) {
        int r = 3 * j + c;
        y[c] = sb[r] + xn[0] * sw[3 * r] + xn[1] * sw[3 * r + 1] + xn[2] * sw[3 * r + 2];
    }
}

__global__ void __launch_bounds__(NT) k_upconv(
    const float* __restrict__ x4, const float* __restrict__ w,
    const float* __restrict__ b, const int* __restrict__ top,
    const int* __restrict__ down, int R, int Nout, float* __restrict__ out,
    const float* __restrict__ bng, const float* __restrict__ bnb,
    int phase, int nb, float n) {
    __shared__ float sw[63], sb[21], sp[16], s_acc[16];
    int tid = threadIdx.x;
    load_sp(sp);
    if (tid < 63) sw[tid] = w[tid];
    if (tid < 21) sb[tid] = b[tid];
    if (tid < 16) s_acc[tid] = 0.f;
    __syncthreads();

    int t = blockIdx.x * NT + tid;
    float vals[3] = {0.f, 0.f, 0.f};
    if (t < Nout) {
        if (t < R) {
            yrow(x4, sw, sb, sp, __ldg(&top[t]), vals);
        } else {
            int e = t - R;
            int i0 = __ldg(&down[2 * e]), i1 = __ldg(&down[2 * e + 1]);
            float ya[3], yb[3];
            yrow(x4, sw, sb, sp, i0, ya);
            yrow(x4, sw, sb, sp, i1, yb);
            vals[0] = 0.5f * (ya[0] + ya[1]);
            vals[1] = 0.5f * (ya[2] + yb[0]);
            vals[2] = 0.5f * (yb[1] + yb[2]);
        }
        reinterpret_cast<float4*>(out)[t] = make_float4(vals[0], vals[1], vals[2], 0.f);
    }
    float s2[3] = {vals[0] * vals[0], vals[1] * vals[1], vals[2] * vals[2]};
    stats_publish<3>(vals, s2, s_acc, nb, n, bng, bnb, phase);
}

// ---------------------------------------------------------------------------
// One-ring conv. CING = float4 groups per input vertex (1: padded 3ch stride4,
// 2: 8ch stride8). 2 vertices/thread for weight-register reuse; float4 LDS.
// OSTR: 8 = padded float4x2 out, 2 = float2 out (final).
// ---------------------------------------------------------------------------
template <int CING>
__device__ __forceinline__ void load_norm(const float* __restrict__ x,
                                          int v, const float* sp, float* xn) {
#pragma unroll
    for (int g4 = 0; g4 < CING; g4++) {
        float4 xv = __ldg(reinterpret_cast<const float4*>(x) + v * CING + g4);
        float raw[4] = {xv.x, xv.y, xv.z, xv.w};
#pragma unroll
        for (int c = 0; c < 4; c++) {
            float t = raw[c] * sp[4 * g4 + c] + sp[8 + 4 * g4 + c];
            xn[4 * g4 + c] = t >= 0.f ? t : SLOPE * t;
        }
    }
}

template <int CING, int COUT, bool PUB, int OSTR>
__global__ void __launch_bounds__(NT) k_onering(
    const float* __restrict__ x, const float* __restrict__ w,
    const float* __restrict__ b, const int* __restrict__ neigh,
    float* __restrict__ out,
    const float* __restrict__ bng, const float* __restrict__ bnb,
    int phase, int nb, float n) {
    __shared__ float4 sw4[COUT * 7 * CING];
    __shared__ float sb[COUT], sp[16], s_acc[16];
    int tid = threadIdx.x;
    load_sp(sp);
    for (int i = tid; i < COUT * 7; i += NT) {
        int o = i / 7, j = i - 7 * o;
        if (CING == 1) {
            sw4[i] = make_float4(w[o * 21 + j * 3], w[o * 21 + j * 3 + 1],
                                 w[o * 21 + j * 3 + 2], 0.f);
        } else {
            const float4* wp = reinterpret_cast<const float4*>(w) + i * 2;
            sw4[i * 2] = wp[0];
            sw4[i * 2 + 1] = wp[1];
        }
    }
    if (tid < COUT) sb[tid] = b[tid];
    if (tid < 16) s_acc[tid] = 0.f;
    __syncthreads();

    int v0 = blockIdx.x * (2 * NT) + tid;
    int v1 = v0 + NT;
    bool a0 = v0 < N3, a1 = v1 < N3;

    float acc0[COUT], acc1[COUT];
#pragma unroll
    for (int o = 0; o < COUT; o++) { acc0[o] = sb[o]; acc1[o] = sb[o]; }

#pragma unroll
    for (int j = 0; j < 7; j++) {
        int n0 = a0 ? __ldg(&neigh[7 * v0 + j]) : 0;
        int n1 = a1 ? __ldg(&neigh[7 * v1 + j]) : 0;
        float xn0[4 * CING], xn1[4 * CING];
        load_norm<CING>(x, n0, sp, xn0);
        load_norm<CING>(x, n1, sp, xn1);
#pragma unroll
        for (int o = 0; o < COUT; o++) {
#pragma unroll
            for (int g4 = 0; g4 < CING; g4++) {
                float4 w4 = sw4[(o * 7 + j) * CING + g4];
                acc0[o] += w4.x * xn0[4 * g4] + w4.y * xn0[4 * g4 + 1] +
                           w4.z * xn0[4 * g4 + 2] + w4.w * xn0[4 * g4 + 3];
                acc1[o] += w4.x * xn1[4 * g4] + w4.y * xn1[4 * g4 + 1] +
                           w4.z * xn1[4 * g4 + 2] + w4.w * xn1[4 * g4 + 3];
            }
        }
    }

    if (OSTR == 8) {
        if (a0) {
            float4* po = reinterpret_cast<float4*>(out) + 2 * v0;
            po[0] = make_float4(acc0[0], acc0[1], acc0[2], acc0[3]);
            po[1] = make_float4(acc0[4 % COUT], acc0[5 % COUT], acc0[6 % COUT], acc0[7 % COUT]);
        }
        if (a1) {
            float4* po = reinterpret_cast<float4*>(out) + 2 * v1;
            po[0] = make_float4(acc1[0], acc1[1], acc1[2], acc1[3]);
            po[1] = make_float4(acc1[4 % COUT], acc1[5 % COUT], acc1[6 % COUT], acc1[7 % COUT]);
        }
    } else {
        if (a0) reinterpret_cast<float2*>(out)[v0] = make_float2(acc0[0], acc0[1]);
        if (a1) reinterpret_cast<float2*>(out)[v1] = make_float2(acc1[0], acc1[1]);
    }

    if (PUB) {
        float s1[COUT], s2[COUT];
#pragma unroll
        for (int o = 0; o < COUT; o++) {
            s1[o] = (a0 ? acc0[o] : 0.f) + (a1 ? acc1[o] : 0.f);
            s2[o] = (a0 ? acc0[o] * acc0[o] : 0.f) + (a1 ? acc1[o] * acc1[o] : 0.f);
        }
        stats_publish<COUT>(s1, s2, s_acc, nb, n, bng, bnb, phase);
    }
}

// ---------------------------------------------------------------------------
// 6 launches, graph-capturable, no separate finalize kernels.
// ---------------------------------------------------------------------------
extern "C" void kernel_launch(void* const* d_in, const int* in_sizes, int n_in,
                              void* d_out, int out_size) {
    const float* age   = (const float*)d_in[0];
    const float* aw    = (const float*)d_in[1];
    const float* ab    = (const float*)d_in[2];
    const float* fcw   = (const float*)d_in[3];
    const float* fcb   = (const float*)d_in[4];
    const float* bnu0g = (const float*)d_in[5];
    const float* bnu0b = (const float*)d_in[6];
    const float* u0w   = (const float*)d_in[7];
    const float* u0b   = (const float*)d_in[8];
    const float* bnu1g = (const float*)d_in[9];
    const float* bnu1b = (const float*)d_in[10];
    const float* u1w   = (const float*)d_in[11];
    const float* u1b   = (const float*)d_in[12];
    const float* bn0g  = (const float*)d_in[13];
    const float* bn0b  = (const float*)d_in[14];
    const float* c0w   = (const float*)d_in[15];
    const float* c0b   = (const float*)d_in[16];
    const float* bn1g  = (const float*)d_in[17];
    const float* bn1b  = (const float*)d_in[18];
    const float* c1w   = (const float*)d_in[19];
    const float* c1b   = (const float*)d_in[20];
    const float* bn2g  = (const float*)d_in[21];
    const float* bn2b  = (const float*)d_in[22];
    const float* c2w   = (const float*)d_in[23];
    const float* c2b   = (const float*)d_in[24];
    const int* top0    = (const int*)d_in[25];
    const int* down0   = (const int*)d_in[26];
    const int* top1    = (const int*)d_in[27];
    const int* down1   = (const int*)d_in[28];
    const int* neigh   = (const int*)d_in[29];

    float *xA, *xB;
    cudaGetSymbolAddress((void**)&xA, g_xA);
    cudaGetSymbolAddress((void**)&xB, g_xB);

    int nb1 = (N1 + NT - 1) / NT;        // 41
    int nb2 = (N2 + NT - 1) / NT;        // 161
    int nb3 = (N3 + NT - 1) / NT;        // 641
    int nbo = (N3 + 2 * NT - 1) / (2 * NT);  // 321

    // K1: fc -> xA(stride4); stats for bn_up0 (phase 0)
    k_fc<<<nb1, NT>>>(age, aw, ab, fcw, fcb, xA, bnu0g, bnu0b);

    // K2: upconv0 xA -> xB(stride4); stats bn_up1 (phase 1)
    k_upconv<<<nb2, NT>>>(xA, u0w, u0b, top0, down0, N1, N2, xB,
                          bnu1g, bnu1b, 1, nb2, (float)N2);

    // K3: upconv1 xB -> xA(stride4); stats bn0 (phase 2)
    k_upconv<<<nb3, NT>>>(xB, u1w, u1b, top1, down1, N2, N3, xA,
                          bn0g, bn0b, 2, nb3, (float)N3);

    // K4: onering 3->8  xA -> xB(stride8); stats bn1 (phase 3)
    k_onering<1, 8, true, 8><<<nbo, NT>>>(xA, c0w, c0b, neigh, xB,
                                          bn1g, bn1b, 3, nbo, (float)N3);

    // K5: onering 8->8  xB -> xA(stride8); stats bn2 (phase 4)
    k_onering<2, 8, true, 8><<<nbo, NT>>>(xB, c1w, c1b, neigh, xA,
                                          bn2g, bn2b, 4, nbo, (float)N3);

    // K6: onering 8->2  xA -> d_out
    k_onering<2, 2, false, 2><<<nbo, NT>>>(xA, c2w, c2b, neigh, (float*)d_out,
                                           nullptr, nullptr, 5, nbo, (float)N3);
}